// round 16
// baseline (speedup 1.0000x reference)
#include <cuda_runtime.h>
#include <cuda_fp16.h>
#include <cstdint>

#define Bsz 2
#define S   2048
#define D   1024
#define H   16
#define HD  64

// ---------------- scratch (__device__ globals; alloc-free rule) -------------
__device__ __align__(16) __half g_xh[(size_t)Bsz * S * D];   // x fp16 single
__device__ __align__(16) __half g_w1[(size_t)2 * D * D];     // in_proj_w[0:2D]
__device__ __align__(16) __half g_w3[(size_t)D * D];         // out_w
__device__ __align__(16) __half g_qk[(size_t)Bsz * S * 2 * D]; // Q(scaled)|K fp16
__device__ __align__(16) __half g_vh[(size_t)Bsz * S * D];   // V fp16
__device__ uint32_t g_mb[262144];                            // packed mask bits
__device__ __align__(16) __half g_ath[(size_t)Bsz * S * D];  // attention out fp16

// ---------------- helpers (all plain sm_80+ PTX; no 'a' features) -----------
__device__ __forceinline__ uint32_t smem_u32(const void* p) {
    uint32_t a;
    asm("{ .reg .u64 t; cvta.to.shared.u64 t, %1; cvt.u32.u64 %0, t; }" : "=r"(a) : "l"(p));
    return a;
}
__device__ __forceinline__ void cp16(uint32_t dst, const void* src) {
    asm volatile("cp.async.cg.shared.global [%0], [%1], 16;" :: "r"(dst), "l"(src));
}
__device__ __forceinline__ void cp_commit() {
    asm volatile("cp.async.commit_group;" ::: "memory");
}
__device__ __forceinline__ void cp_wait0() {
    asm volatile("cp.async.wait_group 0;" ::: "memory");
}
__device__ __forceinline__ void cp_wait1() {
    asm volatile("cp.async.wait_group 1;" ::: "memory");
}
__device__ __forceinline__ void cp_wait2() {
    asm volatile("cp.async.wait_group 2;" ::: "memory");
}
__device__ __forceinline__ void ldsm_x4(uint32_t (&r)[4], uint32_t addr) {
    asm volatile("ldmatrix.sync.aligned.m8n8.x4.shared.b16 {%0,%1,%2,%3}, [%4];"
                 : "=r"(r[0]), "=r"(r[1]), "=r"(r[2]), "=r"(r[3]) : "r"(addr));
}
__device__ __forceinline__ void ldsm_x4_t(uint32_t (&r)[4], uint32_t addr) {
    asm volatile("ldmatrix.sync.aligned.m8n8.x4.trans.shared.b16 {%0,%1,%2,%3}, [%4];"
                 : "=r"(r[0]), "=r"(r[1]), "=r"(r[2]), "=r"(r[3]) : "r"(addr));
}
__device__ __forceinline__ void mma16816h(float (&c)[4], const uint32_t (&a)[4],
                                          uint32_t b0, uint32_t b1) {
    asm volatile(
        "mma.sync.aligned.m16n8k16.row.col.f32.f16.f16.f32 "
        "{%0,%1,%2,%3}, {%4,%5,%6,%7}, {%8,%9}, {%0,%1,%2,%3};"
        : "+f"(c[0]), "+f"(c[1]), "+f"(c[2]), "+f"(c[3])
        : "r"(a[0]), "r"(a[1]), "r"(a[2]), "r"(a[3]), "r"(b0), "r"(b1));
}
__device__ __forceinline__ uint32_t h2pack_sat(float lo, float hi) {
    uint32_t r;
    asm("cvt.rn.satfinite.f16x2.f32 %0, %1, %2;" : "=r"(r) : "f"(hi), "f"(lo));
    return r;
}
__device__ __forceinline__ float ex2(float x) {
    float r;
    asm("ex2.approx.f32 %0, %1;" : "=f"(r) : "f"(x));
    return r;
}
__device__ __forceinline__ void single_store_h(__half* Oh, size_t idx,
                                               float v0, float v1) {
    __half2 a; a.x = __float2half_rn(v0); a.y = __float2half_rn(v1);
    *(__half2*)(Oh + idx) = a;
}
__device__ __forceinline__ uint32_t cvt2h(float a, float b) {
    uint32_t r;
    asm("cvt.rn.f16x2.f32 %0, %1, %2;" : "=r"(r) : "f"(b), "f"(a));
    return r;
}

// ---------------------------------------------------------------------------
// Fused pre-pass: x, w1, w3, V -> fp16 (4 float4s/thread, MLP=4); mask bit-pack.
// ---------------------------------------------------------------------------
#define CN1 1048576   // x  float4s
#define CN2 524288    // w1
#define CN3 262144    // w3
#define CN4 1048576   // V
#define CNT (CN1 + CN2 + CN3 + CN4)
#define NC4 (CNT / 4)          // 720896 conv super-items (4 float4s each)
#define CNM 262144             // mask words
#define CNTOT2 (NC4 + CNM)     // 983040

__global__ __launch_bounds__(256)
void conv_all(const float* __restrict__ x, const float* __restrict__ w1,
              const float* __restrict__ w3, const float* __restrict__ Vin,
              const float* __restrict__ Min) {
    int i = blockIdx.x * 256 + threadIdx.x;
    if (i >= CNTOT2) return;
    if (i >= NC4) {
        // mask bit-pack: idx = (((b*128+qg)*8+r8)*32+it)*4+lg
        int idx = i - NC4;
        int lg = idx & 3, it = (idx >> 2) & 31, r8 = (idx >> 7) & 7;
        int qg = (idx >> 10) & 127, b = idx >> 17;
        const float* base = Min + ((size_t)b * S + qg * 16 + r8) * S + it * 64 + lg * 2;
        uint32_t w = 0;
        #pragma unroll
        for (int j = 0; j < 8; j++) {
            float2 a = *(const float2*)(base + j * 8);
            float2 c = *(const float2*)(base + (size_t)8 * S + j * 8);
            if (a.x != 0.f) w |= 1u << (2 * j);
            if (a.y != 0.f) w |= 1u << (2 * j + 1);
            if (c.x != 0.f) w |= 1u << (16 + 2 * j);
            if (c.y != 0.f) w |= 1u << (17 + 2 * j);
        }
        g_mb[idx] = w;
        return;
    }
    // conv: 4 consecutive float4s (all within one array; boundaries % 4 == 0)
    int j = i * 4;
    const float* src;
    __half* o;
    if (j < CN1) { src = x; o = g_xh; }
    else if ((j -= CN1) < CN2) { src = w1; o = g_w1; }
    else if ((j -= CN2) < CN3) { src = w3; o = g_w3; }
    else { j -= CN3; src = Vin; o = g_vh; }
    const float4* s4 = (const float4*)src + j;
    float4 v0 = s4[0], v1 = s4[1], v2 = s4[2], v3 = s4[3];
    uint4 o0, o1;
    o0.x = cvt2h(v0.x, v0.y); o0.y = cvt2h(v0.z, v0.w);
    o0.z = cvt2h(v1.x, v1.y); o0.w = cvt2h(v1.z, v1.w);
    o1.x = cvt2h(v2.x, v2.y); o1.y = cvt2h(v2.z, v2.w);
    o1.z = cvt2h(v3.x, v3.y); o1.w = cvt2h(v3.z, v3.w);
    uint4* dst = (uint4*)(o + (size_t)j * 4);
    dst[0] = o0;
    dst[1] = o1;
}

// ---------------------------------------------------------------------------
// fp16 single GEMM: C = A[M][K] * B[N][K]^T + bias
// 128x128 tile, BK=32, cp.async 4-stage pipeline, 8 warps, one barrier/chunk.
// Odd warps traverse kk in reverse order -> LDS/tensor phases staggered.
// mode 0: fp32 out to Cf. mode 1: fp16 single out; Q cols scaled 0.125*log2e.
// ---------------------------------------------------------------------------
#define GEMM_SMEM (4 * 10240 * 2)   // 4 buffers x 20480 bytes
#define QSC 0.1803368801111204f     // 0.125 * log2(e)

__device__ __forceinline__ void gemm_issue(
    const __half* A, const __half* Bw,
    int K, int row0, int col0, int chunk, uint32_t dstbase, int tid) {
    #pragma unroll
    for (int j = 0; j < 4; j++) {
        int linear = tid + j * 256;
        int arr = linear >> 9, rem = linear & 511;
        int r = rem >> 2, c = rem & 3;
        const __half* src = arr ? Bw : A;
        int grow = (arr ? col0 : row0) + r;
        cp16(dstbase + (uint32_t)(arr * 5120 + r * 40 + c * 8) * 2,
             src + (size_t)grow * K + chunk * 32 + c * 8);
    }
}

__global__ __launch_bounds__(256, 2)
void mma_gemm(const __half* __restrict__ A, const __half* __restrict__ Bw,
              const float* __restrict__ bias, float* __restrict__ Cf,
              __half* __restrict__ Oh, int K, int N, int mode) {
    extern __shared__ __half smem[];
    const int tid = threadIdx.x;
    const int wid = tid >> 5, lane = tid & 31;
    const int wr = wid >> 2, wc = wid & 3;
    const int wpar = wid & 1;   // phase stagger parity
    const int row0 = blockIdx.y * 128, col0 = blockIdx.x * 128;
    const uint32_t sb = smem_u32(smem);

    float acc[4][4][4] = {};

    const int nch = K / 32;
    gemm_issue(A, Bw, K, row0, col0, 0, sb, tid);               cp_commit();
    gemm_issue(A, Bw, K, row0, col0, 1, sb + 20480u, tid);      cp_commit();
    gemm_issue(A, Bw, K, row0, col0, 2, sb + 40960u, tid);      cp_commit();

    for (int ch = 0; ch < nch; ++ch) {
        if (ch < nch - 2)       cp_wait2();
        else if (ch == nch - 2) cp_wait1();
        else                    cp_wait0();
        __syncthreads();

        if (ch + 3 < nch) {
            gemm_issue(A, Bw, K, row0, col0, ch + 3,
                       sb + (uint32_t)((ch + 3) & 3) * 20480u, tid);
            cp_commit();
        }

        const uint32_t bufb = sb + (uint32_t)(ch & 3) * 20480u;
        #pragma unroll
        for (int kx = 0; kx < 2; kx++) {
            const int kk = kx ^ wpar;   // odd warps reverse kk order
            const uint32_t koffs = (uint32_t)(kk * 16 + (lane >> 4) * 8);
            uint32_t b0[4], b1[4];
            ldsm_x4(b0, bufb + (5120u + (uint32_t)((wc * 32 + (lane & 15)) * 40) + koffs) * 2);
            ldsm_x4(b1, bufb + (5120u + (uint32_t)((wc * 32 + 16 + (lane & 15)) * 40) + koffs) * 2);
            #pragma unroll
            for (int i = 0; i < 4; i++) {
                uint32_t a4[4];
                ldsm_x4(a4, bufb + ((uint32_t)((wr * 64 + i * 16 + (lane & 15)) * 40) + koffs) * 2);
                mma16816h(acc[i][0], a4, b0[0], b0[2]);
                mma16816h(acc[i][1], a4, b0[1], b0[3]);
                mma16816h(acc[i][2], a4, b1[0], b1[2]);
                mma16816h(acc[i][3], a4, b1[1], b1[3]);
            }
        }
    }

    const float qs = (mode == 1 && col0 < D) ? QSC : 1.0f;
    #pragma unroll
    for (int j = 0; j < 4; j++) {
        const int col = col0 + wc * 32 + j * 8 + (lane & 3) * 2;
        const float b0 = bias[col], b1 = bias[col + 1];
        #pragma unroll
        for (int i = 0; i < 4; i++) {
            const int row = row0 + wr * 64 + i * 16 + (lane >> 2);
            float v0 = (acc[i][j][0] + b0) * qs, v1 = (acc[i][j][1] + b1) * qs;
            float w0 = (acc[i][j][2] + b0) * qs, w1 = (acc[i][j][3] + b1) * qs;
            if (mode == 0) {
                *(float2*)(Cf + (size_t)row * N + col) = make_float2(v0, v1);
                *(float2*)(Cf + (size_t)(row + 8) * N + col) = make_float2(w0, w1);
            } else {
                single_store_h(Oh, (size_t)row * N + col, v0, v1);
                single_store_h(Oh, (size_t)(row + 8) * N + col, w0, w1);
            }
        }
    }
}

// ---------------------------------------------------------------------------
// Attention (fp16 mma, all-single). Per CTA: 128 q rows; 8 warps x 16q x 64k,
// two independent 32-key halves; odd warps traverse halves in reverse order
// so MUFU (ex2) of one warp overlaps HMMA of its SMSP neighbors post-barrier.
// Bitmask masking, scalar Zm. Q pre-scaled 0.125*log2e; e = ex2(s).
// 3-deep KV ring -> ONE barrier per iteration.
// smem halves: Q@0 (9216), 3 KV buffers @9216 stride 9216 (K@0, V@4608).
// ---------------------------------------------------------------------------
#define ATTN_SMEM ((9216 + 3 * 9216) * 2)

__device__ __forceinline__ void attn_issue_kv(int b, int h, int it, uint32_t sb,
                                              int p, int tid) {
    const int k0 = it * 64;
    #pragma unroll
    for (int j = 0; j < 4; j++) {
        int linear = tid + j * 256;
        int arr = linear >> 9, rem = linear & 511;
        int r = rem >> 3, c = rem & 7;
        const __half* src = arr
            ? g_vh + (size_t)(b * S + k0 + r) * 1024 + h * 64 + c * 8
            : g_qk + (size_t)(b * S + k0 + r) * 2048 + D + h * 64 + c * 8;
        cp16(sb + (uint32_t)(9216 + p * 9216 + arr * 4608 + r * 72 + c * 8) * 2, src);
    }
}

__global__ __launch_bounds__(256, 2)
void attn_mma() {
    extern __shared__ __half smh[];
    const int tid = threadIdx.x;
    const int wid = tid >> 5, lane = tid & 31;
    const int b = blockIdx.z, h = blockIdx.y;
    const int q0 = blockIdx.x * 128;
    const uint32_t sb = smem_u32(smh);

    // Q -> smem (same commit group as iter-0 K/V)
    #pragma unroll
    for (int j = 0; j < 4; j++) {
        int linear = tid + j * 256;
        int r = linear >> 3, c = linear & 7;
        cp16(sb + (uint32_t)(r * 72 + c * 8) * 2,
             g_qk + (size_t)(b * S + q0 + r) * 2048 + h * 64 + c * 8);
    }
    attn_issue_kv(b, h, 0, sb, 0, tid);
    cp_commit();

    float Oc[8][4] = {};
    float zm0 = 0.f, zm1 = 0.f;
    uint32_t qh[4][4];   // static Q frags, loaded once at it==0
    int p = 0;
    const int wpar = wid & 1;

    const uint32_t qrow_off = (uint32_t)((wid * 16 + (lane & 15)) * 72 + (lane >> 4) * 8);
    const uint32_t* mp = g_mb
        + (size_t)((b * 128 + blockIdx.x * 8 + wid) * 8 + (lane >> 2)) * 128 + (lane & 3);

    const int niter = S / 64;
    for (int it = 0; it < niter; ++it) {
        const int pn = (p + 1 == 3) ? 0 : p + 1;
        if (it + 1 < niter) {
            attn_issue_kv(b, h, it + 1, sb, pn, tid);
            cp_commit();
            cp_wait1();
        } else {
            cp_wait0();
        }

        const uint32_t mw = mp[it * 4];   // 4B bitmask, prefetched pre-barrier

        __syncthreads();   // KV buffer p (and at it=0, Q) ready; single barrier

        if (it == 0) {
            #pragma unroll
            for (int kk = 0; kk < 4; kk++)
                ldsm_x4(qh[kk], sb + (qrow_off + (uint32_t)(kk * 16)) * 2);
        }

        const uint32_t kvb = 9216u + (uint32_t)p * 9216u;

        // two independent 32-key halves; odd warps start with the other half
        #pragma unroll
        for (int hh = 0; hh < 2; hh++) {
            const int hf = hh ^ wpar;

            // scores for keys [hf*32, hf*32+32)
            float sc[4][4] = {};
            #pragma unroll
            for (int jj = 0; jj < 2; jj++) {
                const int jp = hf * 2 + jj;
                const uint32_t krow = (uint32_t)((jp * 16 + (lane & 15)) * 72
                                                 + (lane >> 4) * 8);
                #pragma unroll
                for (int kk = 0; kk < 4; kk++) {
                    uint32_t kh[4];
                    ldsm_x4(kh, sb + (kvb + krow + (uint32_t)(kk * 16)) * 2);
                    mma16816h(sc[jj * 2 + 0], qh[kk], kh[0], kh[2]);
                    mma16816h(sc[jj * 2 + 1], qh[kk], kh[1], kh[3]);
                }
            }

            // ex2 + bit-mask + Zm + pack P into a-frags
            uint32_t pa[2][4];
            #pragma unroll
            for (int j = 0; j < 4; j++) {
                const int jg = hf * 4 + j;
                float e0 = ex2(sc[j][0]);
                float e1 = ex2(sc[j][1]);
                float e2 = ex2(sc[j][2]);
                float e3 = ex2(sc[j][3]);
                float em0 = (mw & (1u << (2 * jg)))      ? e0 : 0.0f;
                float em1 = (mw & (1u << (2 * jg + 1)))  ? e1 : 0.0f;
                float em2 = (mw & (1u << (16 + 2 * jg))) ? e2 : 0.0f;
                float em3 = (mw & (1u << (17 + 2 * jg))) ? e3 : 0.0f;
                zm0 += em0 + em1; zm1 += em2 + em3;
                pa[j >> 1][(j & 1) * 2 + 0] = h2pack_sat(em0, em1);
                pa[j >> 1][(j & 1) * 2 + 1] = h2pack_sat(em2, em3);
            }

            // PV for key rows [hf*32, hf*32+32)
            #pragma unroll
            for (int j2 = 0; j2 < 2; j2++) {
                const int j2g = hf * 2 + j2;
                const uint32_t vrow = (uint32_t)((j2g * 16 + ((lane >> 3) & 1) * 8
                                                  + (lane & 7)) * 72 + (lane >> 4) * 8);
                #pragma unroll
                for (int ndp = 0; ndp < 4; ndp++) {
                    uint32_t vh[4];
                    ldsm_x4_t(vh, sb + (kvb + 4608u + vrow + (uint32_t)(ndp * 16)) * 2);
                    mma16816h(Oc[ndp * 2 + 0], pa[j2], vh[0], vh[1]);
                    mma16816h(Oc[ndp * 2 + 1], pa[j2], vh[2], vh[3]);
                }
            }
        }
        p = pn;
    }

    // quad reduce Zm (lanes sharing lane>>2 hold the same rows)
    #pragma unroll
    for (int off = 1; off < 4; off <<= 1) {
        zm0 += __shfl_xor_sync(0xffffffffu, zm0, off);
        zm1 += __shfl_xor_sync(0xffffffffu, zm1, off);
    }
    const float inv0 = 1.0f / zm0;
    const float inv1 = 1.0f / zm1;

    const int row = b * S + q0 + wid * 16 + (lane >> 2);
    #pragma unroll
    for (int nd = 0; nd < 8; nd++) {
        const int col = h * 64 + nd * 8 + (lane & 3) * 2;
        single_store_h(g_ath, (size_t)row * D + col,
                       Oc[nd][0] * inv0, Oc[nd][1] * inv0);
        single_store_h(g_ath, (size_t)(row + 8) * D + col,
                       Oc[nd][2] * inv1, Oc[nd][3] * inv1);
    }
}

// ---------------------------------------------------------------------------
extern "C" void kernel_launch(void* const* d_in, const int* in_sizes, int n_in,
                              void* d_out, int out_size) {
    const float* x         = (const float*)d_in[0];  // [B,S,D]
    const float* Vin       = (const float*)d_in[1];  // [B,S,H,HD]
    const float* Min       = (const float*)d_in[2];  // [B,S,S]
    const float* in_proj_w = (const float*)d_in[3];  // [3D,D]
    const float* in_proj_b = (const float*)d_in[4];  // [3D]
    const float* out_w     = (const float*)d_in[5];  // [D,D]
    const float* out_b     = (const float*)d_in[6];  // [D]
    float* out             = (float*)d_out;          // [B,S,D]

    __half *xh, *w1, *w3, *qk, *ath;
    cudaGetSymbolAddress((void**)&xh,  g_xh);
    cudaGetSymbolAddress((void**)&w1,  g_w1);
    cudaGetSymbolAddress((void**)&w3,  g_w3);
    cudaGetSymbolAddress((void**)&qk,  g_qk);
    cudaGetSymbolAddress((void**)&ath, g_ath);

    cudaFuncSetAttribute(mma_gemm, cudaFuncAttributeMaxDynamicSharedMemorySize, GEMM_SMEM);
    cudaFuncSetAttribute(attn_mma, cudaFuncAttributeMaxDynamicSharedMemorySize, ATTN_SMEM);

    const int Mtot = Bsz * S;  // 4096

    // fused conversions (MLP=4) + mask bit-pack (one launch)
    conv_all<<<(CNTOT2 + 255) / 256, 256>>>(x, in_proj_w, out_w, Vin, Min);

    // Stage 1: [Q|K] = x @ in_proj_w[0:2D]^T + b -> fp16 single (Q scaled)
    mma_gemm<<<dim3((2 * D) / 128, Mtot / 128), 256, GEMM_SMEM>>>(
        xh, w1, in_proj_b, nullptr, qk, D, 2 * D, 1);

    // Stage 2: masked-renormalized attention -> fp16 single [4096][1024]
    attn_mma<<<dim3(S / 128, H, Bsz), 256, ATTN_SMEM>>>();

    // Stage 3: out = attn @ out_w^T + out_b  (fp32)
    mma_gemm<<<dim3(D / 128, Mtot / 128), 256, GEMM_SMEM>>>(
        ath, w3, out_b, out, nullptr, D, D, 0);
}

// round 17
// speedup vs baseline: 1.0379x; 1.0379x over previous
#include <cuda_runtime.h>
#include <cuda_fp16.h>
#include <cstdint>

#define Bsz 2
#define S   2048
#define D   1024
#define H   16
#define HD  64

// ---------------- scratch (__device__ globals; alloc-free rule) -------------
__device__ __align__(16) __half g_xh[(size_t)Bsz * S * D];   // x fp16 single
__device__ __align__(16) __half g_w1[(size_t)2 * D * D];     // in_proj_w[0:2D]
__device__ __align__(16) __half g_w3[(size_t)D * D];         // out_w
__device__ __align__(16) __half g_qk[(size_t)Bsz * S * 2 * D]; // Q(scaled)|K fp16
__device__ __align__(16) __half g_vh[(size_t)Bsz * S * D];   // V fp16
__device__ uint32_t g_mb[262144];                            // packed mask bits
__device__ __align__(16) __half g_ath[(size_t)Bsz * S * D];  // attention out fp16

// ---------------- helpers (all plain sm_80+ PTX; no 'a' features) -----------
__device__ __forceinline__ uint32_t smem_u32(const void* p) {
    uint32_t a;
    asm("{ .reg .u64 t; cvta.to.shared.u64 t, %1; cvt.u32.u64 %0, t; }" : "=r"(a) : "l"(p));
    return a;
}
__device__ __forceinline__ void cp16(uint32_t dst, const void* src) {
    asm volatile("cp.async.cg.shared.global [%0], [%1], 16;" :: "r"(dst), "l"(src));
}
__device__ __forceinline__ void cp_commit() {
    asm volatile("cp.async.commit_group;" ::: "memory");
}
__device__ __forceinline__ void cp_wait0() {
    asm volatile("cp.async.wait_group 0;" ::: "memory");
}
__device__ __forceinline__ void cp_wait1() {
    asm volatile("cp.async.wait_group 1;" ::: "memory");
}
__device__ __forceinline__ void cp_wait2() {
    asm volatile("cp.async.wait_group 2;" ::: "memory");
}
__device__ __forceinline__ void ldsm_x4(uint32_t (&r)[4], uint32_t addr) {
    asm volatile("ldmatrix.sync.aligned.m8n8.x4.shared.b16 {%0,%1,%2,%3}, [%4];"
                 : "=r"(r[0]), "=r"(r[1]), "=r"(r[2]), "=r"(r[3]) : "r"(addr));
}
__device__ __forceinline__ void ldsm_x4_t(uint32_t (&r)[4], uint32_t addr) {
    asm volatile("ldmatrix.sync.aligned.m8n8.x4.trans.shared.b16 {%0,%1,%2,%3}, [%4];"
                 : "=r"(r[0]), "=r"(r[1]), "=r"(r[2]), "=r"(r[3]) : "r"(addr));
}
__device__ __forceinline__ void mma16816h(float (&c)[4], const uint32_t (&a)[4],
                                          uint32_t b0, uint32_t b1) {
    asm volatile(
        "mma.sync.aligned.m16n8k16.row.col.f32.f16.f16.f32 "
        "{%0,%1,%2,%3}, {%4,%5,%6,%7}, {%8,%9}, {%0,%1,%2,%3};"
        : "+f"(c[0]), "+f"(c[1]), "+f"(c[2]), "+f"(c[3])
        : "r"(a[0]), "r"(a[1]), "r"(a[2]), "r"(a[3]), "r"(b0), "r"(b1));
}
__device__ __forceinline__ uint32_t h2pack_sat(float lo, float hi) {
    uint32_t r;
    asm("cvt.rn.satfinite.f16x2.f32 %0, %1, %2;" : "=r"(r) : "f"(hi), "f"(lo));
    return r;
}
__device__ __forceinline__ float ex2(float x) {
    float r;
    asm("ex2.approx.f32 %0, %1;" : "=f"(r) : "f"(x));
    return r;
}
__device__ __forceinline__ void single_store_h(__half* Oh, size_t idx,
                                               float v0, float v1) {
    __half2 a; a.x = __float2half_rn(v0); a.y = __float2half_rn(v1);
    *(__half2*)(Oh + idx) = a;
}
__device__ __forceinline__ uint32_t cvt2h(float a, float b) {
    uint32_t r;
    asm("cvt.rn.f16x2.f32 %0, %1, %2;" : "=r"(r) : "f"(b), "f"(a));
    return r;
}

// ---------------------------------------------------------------------------
// Fused pre-pass: x, w1, w3, V -> fp16 (4 float4s/thread, MLP=4); mask bit-pack.
// ---------------------------------------------------------------------------
#define CN1 1048576   // x  float4s
#define CN2 524288    // w1
#define CN3 262144    // w3
#define CN4 1048576   // V
#define CNT (CN1 + CN2 + CN3 + CN4)
#define NC4 (CNT / 4)          // 720896 conv super-items (4 float4s each)
#define CNM 262144             // mask words
#define CNTOT2 (NC4 + CNM)     // 983040

__global__ __launch_bounds__(256)
void conv_all(const float* __restrict__ x, const float* __restrict__ w1,
              const float* __restrict__ w3, const float* __restrict__ Vin,
              const float* __restrict__ Min) {
    int i = blockIdx.x * 256 + threadIdx.x;
    if (i >= CNTOT2) return;
    if (i >= NC4) {
        // mask bit-pack: idx = (((b*128+qg)*8+r8)*32+it)*4+lg
        int idx = i - NC4;
        int lg = idx & 3, it = (idx >> 2) & 31, r8 = (idx >> 7) & 7;
        int qg = (idx >> 10) & 127, b = idx >> 17;
        const float* base = Min + ((size_t)b * S + qg * 16 + r8) * S + it * 64 + lg * 2;
        uint32_t w = 0;
        #pragma unroll
        for (int j = 0; j < 8; j++) {
            float2 a = *(const float2*)(base + j * 8);
            float2 c = *(const float2*)(base + (size_t)8 * S + j * 8);
            if (a.x != 0.f) w |= 1u << (2 * j);
            if (a.y != 0.f) w |= 1u << (2 * j + 1);
            if (c.x != 0.f) w |= 1u << (16 + 2 * j);
            if (c.y != 0.f) w |= 1u << (17 + 2 * j);
        }
        g_mb[idx] = w;
        return;
    }
    // conv: 4 consecutive float4s (all within one array; boundaries % 4 == 0)
    int j = i * 4;
    const float* src;
    __half* o;
    if (j < CN1) { src = x; o = g_xh; }
    else if ((j -= CN1) < CN2) { src = w1; o = g_w1; }
    else if ((j -= CN2) < CN3) { src = w3; o = g_w3; }
    else { j -= CN3; src = Vin; o = g_vh; }
    const float4* s4 = (const float4*)src + j;
    float4 v0 = s4[0], v1 = s4[1], v2 = s4[2], v3 = s4[3];
    uint4 o0, o1;
    o0.x = cvt2h(v0.x, v0.y); o0.y = cvt2h(v0.z, v0.w);
    o0.z = cvt2h(v1.x, v1.y); o0.w = cvt2h(v1.z, v1.w);
    o1.x = cvt2h(v2.x, v2.y); o1.y = cvt2h(v2.z, v2.w);
    o1.z = cvt2h(v3.x, v3.y); o1.w = cvt2h(v3.z, v3.w);
    uint4* dst = (uint4*)(o + (size_t)j * 4);
    dst[0] = o0;
    dst[1] = o1;
}

// ---------------------------------------------------------------------------
// fp16 single GEMM: C = A[M][K] * B[N][K]^T + bias
// 128x128 tile, BK=32, cp.async 4-stage pipeline, 8 warps, one barrier/chunk.
// mode 0: fp32 out to Cf. mode 1: fp16 single out; Q cols scaled 0.125*log2e.
// ---------------------------------------------------------------------------
#define GEMM_SMEM (4 * 10240 * 2)   // 4 buffers x 20480 bytes
#define QSC 0.1803368801111204f     // 0.125 * log2(e)

__device__ __forceinline__ void gemm_issue(
    const __half* A, const __half* Bw,
    int K, int row0, int col0, int chunk, uint32_t dstbase, int tid) {
    #pragma unroll
    for (int j = 0; j < 4; j++) {
        int linear = tid + j * 256;
        int arr = linear >> 9, rem = linear & 511;
        int r = rem >> 2, c = rem & 3;
        const __half* src = arr ? Bw : A;
        int grow = (arr ? col0 : row0) + r;
        cp16(dstbase + (uint32_t)(arr * 5120 + r * 40 + c * 8) * 2,
             src + (size_t)grow * K + chunk * 32 + c * 8);
    }
}

__global__ __launch_bounds__(256, 2)
void mma_gemm(const __half* __restrict__ A, const __half* __restrict__ Bw,
              const float* __restrict__ bias, float* __restrict__ Cf,
              __half* __restrict__ Oh, int K, int N, int mode) {
    extern __shared__ __half smem[];
    const int tid = threadIdx.x;
    const int wid = tid >> 5, lane = tid & 31;
    const int wr = wid >> 2, wc = wid & 3;
    const int row0 = blockIdx.y * 128, col0 = blockIdx.x * 128;
    const uint32_t sb = smem_u32(smem);

    float acc[4][4][4] = {};

    const int nch = K / 32;
    gemm_issue(A, Bw, K, row0, col0, 0, sb, tid);               cp_commit();
    gemm_issue(A, Bw, K, row0, col0, 1, sb + 20480u, tid);      cp_commit();
    gemm_issue(A, Bw, K, row0, col0, 2, sb + 40960u, tid);      cp_commit();

    for (int ch = 0; ch < nch; ++ch) {
        if (ch < nch - 2)       cp_wait2();
        else if (ch == nch - 2) cp_wait1();
        else                    cp_wait0();
        __syncthreads();

        if (ch + 3 < nch) {
            gemm_issue(A, Bw, K, row0, col0, ch + 3,
                       sb + (uint32_t)((ch + 3) & 3) * 20480u, tid);
            cp_commit();
        }

        const uint32_t bufb = sb + (uint32_t)(ch & 3) * 20480u;
        #pragma unroll
        for (int kk = 0; kk < 2; kk++) {
            const uint32_t koffs = (uint32_t)(kk * 16 + (lane >> 4) * 8);
            uint32_t b0[4], b1[4];
            ldsm_x4(b0, bufb + (5120u + (uint32_t)((wc * 32 + (lane & 15)) * 40) + koffs) * 2);
            ldsm_x4(b1, bufb + (5120u + (uint32_t)((wc * 32 + 16 + (lane & 15)) * 40) + koffs) * 2);
            #pragma unroll
            for (int i = 0; i < 4; i++) {
                uint32_t a4[4];
                ldsm_x4(a4, bufb + ((uint32_t)((wr * 64 + i * 16 + (lane & 15)) * 40) + koffs) * 2);
                mma16816h(acc[i][0], a4, b0[0], b0[2]);
                mma16816h(acc[i][1], a4, b0[1], b0[3]);
                mma16816h(acc[i][2], a4, b1[0], b1[2]);
                mma16816h(acc[i][3], a4, b1[1], b1[3]);
            }
        }
    }

    const float qs = (mode == 1 && col0 < D) ? QSC : 1.0f;
    #pragma unroll
    for (int j = 0; j < 4; j++) {
        const int col = col0 + wc * 32 + j * 8 + (lane & 3) * 2;
        const float b0 = bias[col], b1 = bias[col + 1];
        #pragma unroll
        for (int i = 0; i < 4; i++) {
            const int row = row0 + wr * 64 + i * 16 + (lane >> 2);
            float v0 = (acc[i][j][0] + b0) * qs, v1 = (acc[i][j][1] + b1) * qs;
            float w0 = (acc[i][j][2] + b0) * qs, w1 = (acc[i][j][3] + b1) * qs;
            if (mode == 0) {
                *(float2*)(Cf + (size_t)row * N + col) = make_float2(v0, v1);
                *(float2*)(Cf + (size_t)(row + 8) * N + col) = make_float2(w0, w1);
            } else {
                single_store_h(Oh, (size_t)row * N + col, v0, v1);
                single_store_h(Oh, (size_t)(row + 8) * N + col, w0, w1);
            }
        }
    }
}

// ---------------------------------------------------------------------------
// Attention (fp16 mma, all-single). Per CTA: 128 q rows; 8 warps x 16q x 64k,
// two independent 32-key halves (MUFU of one overlaps HMMA of the other).
// Bitmask masking, scalar Zm. Q pre-scaled 0.125*log2e; e = ex2(s).
// 3-deep KV ring -> ONE barrier per iteration.
// smem halves: Q@0 (9216), 3 KV buffers @9216 stride 9216 (K@0, V@4608).
// ---------------------------------------------------------------------------
#define ATTN_SMEM ((9216 + 3 * 9216) * 2)

__device__ __forceinline__ void attn_issue_kv(int b, int h, int it, uint32_t sb,
                                              int p, int tid) {
    const int k0 = it * 64;
    #pragma unroll
    for (int j = 0; j < 4; j++) {
        int linear = tid + j * 256;
        int arr = linear >> 9, rem = linear & 511;
        int r = rem >> 3, c = rem & 7;
        const __half* src = arr
            ? g_vh + (size_t)(b * S + k0 + r) * 1024 + h * 64 + c * 8
            : g_qk + (size_t)(b * S + k0 + r) * 2048 + D + h * 64 + c * 8;
        cp16(sb + (uint32_t)(9216 + p * 9216 + arr * 4608 + r * 72 + c * 8) * 2, src);
    }
}

__global__ __launch_bounds__(256, 2)
void attn_mma() {
    extern __shared__ __half smh[];
    const int tid = threadIdx.x;
    const int wid = tid >> 5, lane = tid & 31;
    const int b = blockIdx.z, h = blockIdx.y;
    const int q0 = blockIdx.x * 128;
    const uint32_t sb = smem_u32(smh);

    // Q -> smem (same commit group as iter-0 K/V)
    #pragma unroll
    for (int j = 0; j < 4; j++) {
        int linear = tid + j * 256;
        int r = linear >> 3, c = linear & 7;
        cp16(sb + (uint32_t)(r * 72 + c * 8) * 2,
             g_qk + (size_t)(b * S + q0 + r) * 2048 + h * 64 + c * 8);
    }
    attn_issue_kv(b, h, 0, sb, 0, tid);
    cp_commit();

    float Oc[8][4] = {};
    float zm0 = 0.f, zm1 = 0.f;
    uint32_t qh[4][4];   // static Q frags, loaded once at it==0
    int p = 0;

    const uint32_t qrow_off = (uint32_t)((wid * 16 + (lane & 15)) * 72 + (lane >> 4) * 8);
    const uint32_t* mp = g_mb
        + (size_t)((b * 128 + blockIdx.x * 8 + wid) * 8 + (lane >> 2)) * 128 + (lane & 3);

    const int niter = S / 64;
    for (int it = 0; it < niter; ++it) {
        const int pn = (p + 1 == 3) ? 0 : p + 1;
        if (it + 1 < niter) {
            attn_issue_kv(b, h, it + 1, sb, pn, tid);
            cp_commit();
            cp_wait1();
        } else {
            cp_wait0();
        }

        const uint32_t mw = mp[it * 4];   // 4B bitmask, prefetched pre-barrier

        __syncthreads();   // KV buffer p (and at it=0, Q) ready; single barrier

        if (it == 0) {
            #pragma unroll
            for (int kk = 0; kk < 4; kk++)
                ldsm_x4(qh[kk], sb + (qrow_off + (uint32_t)(kk * 16)) * 2);
        }

        const uint32_t kvb = 9216u + (uint32_t)p * 9216u;

        // two independent 32-key halves -> MUFU of one overlaps HMMA of other
        #pragma unroll
        for (int hf = 0; hf < 2; hf++) {
            // scores for keys [hf*32, hf*32+32)
            float sc[4][4] = {};
            #pragma unroll
            for (int jj = 0; jj < 2; jj++) {
                const int jp = hf * 2 + jj;
                const uint32_t krow = (uint32_t)((jp * 16 + (lane & 15)) * 72
                                                 + (lane >> 4) * 8);
                #pragma unroll
                for (int kk = 0; kk < 4; kk++) {
                    uint32_t kh[4];
                    ldsm_x4(kh, sb + (kvb + krow + (uint32_t)(kk * 16)) * 2);
                    mma16816h(sc[jj * 2 + 0], qh[kk], kh[0], kh[2]);
                    mma16816h(sc[jj * 2 + 1], qh[kk], kh[1], kh[3]);
                }
            }

            // ex2 + bit-mask + Zm + pack P into a-frags
            uint32_t pa[2][4];
            #pragma unroll
            for (int j = 0; j < 4; j++) {
                const int jg = hf * 4 + j;
                float e0 = ex2(sc[j][0]);
                float e1 = ex2(sc[j][1]);
                float e2 = ex2(sc[j][2]);
                float e3 = ex2(sc[j][3]);
                float em0 = (mw & (1u << (2 * jg)))      ? e0 : 0.0f;
                float em1 = (mw & (1u << (2 * jg + 1)))  ? e1 : 0.0f;
                float em2 = (mw & (1u << (16 + 2 * jg))) ? e2 : 0.0f;
                float em3 = (mw & (1u << (17 + 2 * jg))) ? e3 : 0.0f;
                zm0 += em0 + em1; zm1 += em2 + em3;
                pa[j >> 1][(j & 1) * 2 + 0] = h2pack_sat(em0, em1);
                pa[j >> 1][(j & 1) * 2 + 1] = h2pack_sat(em2, em3);
            }

            // PV for key rows [hf*32, hf*32+32)
            #pragma unroll
            for (int j2 = 0; j2 < 2; j2++) {
                const int j2g = hf * 2 + j2;
                const uint32_t vrow = (uint32_t)((j2g * 16 + ((lane >> 3) & 1) * 8
                                                  + (lane & 7)) * 72 + (lane >> 4) * 8);
                #pragma unroll
                for (int ndp = 0; ndp < 4; ndp++) {
                    uint32_t vh[4];
                    ldsm_x4_t(vh, sb + (kvb + 4608u + vrow + (uint32_t)(ndp * 16)) * 2);
                    mma16816h(Oc[ndp * 2 + 0], pa[j2], vh[0], vh[1]);
                    mma16816h(Oc[ndp * 2 + 1], pa[j2], vh[2], vh[3]);
                }
            }
        }
        p = pn;
    }

    // quad reduce Zm (lanes sharing lane>>2 hold the same rows)
    #pragma unroll
    for (int off = 1; off < 4; off <<= 1) {
        zm0 += __shfl_xor_sync(0xffffffffu, zm0, off);
        zm1 += __shfl_xor_sync(0xffffffffu, zm1, off);
    }
    const float inv0 = 1.0f / zm0;
    const float inv1 = 1.0f / zm1;

    const int row = b * S + q0 + wid * 16 + (lane >> 2);
    #pragma unroll
    for (int nd = 0; nd < 8; nd++) {
        const int col = h * 64 + nd * 8 + (lane & 3) * 2;
        single_store_h(g_ath, (size_t)row * D + col,
                       Oc[nd][0] * inv0, Oc[nd][1] * inv0);
        single_store_h(g_ath, (size_t)(row + 8) * D + col,
                       Oc[nd][2] * inv1, Oc[nd][3] * inv1);
    }
}

// ---------------------------------------------------------------------------
extern "C" void kernel_launch(void* const* d_in, const int* in_sizes, int n_in,
                              void* d_out, int out_size) {
    const float* x         = (const float*)d_in[0];  // [B,S,D]
    const float* Vin       = (const float*)d_in[1];  // [B,S,H,HD]
    const float* Min       = (const float*)d_in[2];  // [B,S,S]
    const float* in_proj_w = (const float*)d_in[3];  // [3D,D]
    const float* in_proj_b = (const float*)d_in[4];  // [3D]
    const float* out_w     = (const float*)d_in[5];  // [D,D]
    const float* out_b     = (const float*)d_in[6];  // [D]
    float* out             = (float*)d_out;          // [B,S,D]

    __half *xh, *w1, *w3, *qk, *ath;
    cudaGetSymbolAddress((void**)&xh,  g_xh);
    cudaGetSymbolAddress((void**)&w1,  g_w1);
    cudaGetSymbolAddress((void**)&w3,  g_w3);
    cudaGetSymbolAddress((void**)&qk,  g_qk);
    cudaGetSymbolAddress((void**)&ath, g_ath);

    cudaFuncSetAttribute(mma_gemm, cudaFuncAttributeMaxDynamicSharedMemorySize, GEMM_SMEM);
    cudaFuncSetAttribute(attn_mma, cudaFuncAttributeMaxDynamicSharedMemorySize, ATTN_SMEM);

    const int Mtot = Bsz * S;  // 4096

    // fused conversions (MLP=4) + mask bit-pack (one launch)
    conv_all<<<(CNTOT2 + 255) / 256, 256>>>(x, in_proj_w, out_w, Vin, Min);

    // Stage 1: [Q|K] = x @ in_proj_w[0:2D]^T + b -> fp16 single (Q scaled)
    mma_gemm<<<dim3((2 * D) / 128, Mtot / 128), 256, GEMM_SMEM>>>(
        xh, w1, in_proj_b, nullptr, qk, D, 2 * D, 1);

    // Stage 2: masked-renormalized attention -> fp16 single [4096][1024]
    attn_mma<<<dim3(S / 128, H, Bsz), 256, ATTN_SMEM>>>();

    // Stage 3: out = attn @ out_w^T + out_b  (fp32)
    mma_gemm<<<dim3(D / 128, Mtot / 128), 256, GEMM_SMEM>>>(
        ath, w3, out_b, out, nullptr, D, D, 0);
}